// round 1
// baseline (speedup 1.0000x reference)
#include <cuda_runtime.h>
#include <math.h>

// ---------------------------------------------------------------------------
// CNN_51015621542651: 3x (radial-basis conv3d stride2 pad3 size5) + gating,
// spatial mean, fc1+relu, fc2.  Batch 16, input [16,1,64,64,64].
//
// Shapes:
//   L0: in [16,1,64^3]  -> raw [16,23,33^3] -> gated [16,20,33^3]
//   L1: in [16,20,33^3] -> raw [16,23,18^3] -> gated [16,20,18^3]
//   L2: in [16,20,18^3] -> raw [16,20,10^3] (no gate)
//   head: mean over 1000 -> [16,20] -> fc1(50)+relu -> fc2(2) -> [16,2]
// ---------------------------------------------------------------------------

#define N_RAD 3

// scratch (static device globals; no allocation allowed)
__device__ float gB[N_RAD * 125];            // normalized radial basis
__device__ float gK0[23 * 1 * 125];
__device__ float gK1[23 * 20 * 125];
__device__ float gK2[20 * 20 * 125];
__device__ float gA0[16 * 20 * 33 * 33 * 33];   // 11,499,840 floats
__device__ float gA1[16 * 20 * 18 * 18 * 18];   //  1,866,240 floats
__device__ float gA2[16 * 20 * 1000];           //    320,000 floats

__device__ __forceinline__ float sigmoidf_(float x) {
    return 1.0f / (1.0f + expf(-x));
}

// ---------------------------------------------------------------------------
// Radial basis: B_j(t) = exp(-0.5*((r-j)/0.6)^2) / ||B_j||_2   on 5^3 grid
// ---------------------------------------------------------------------------
__global__ void init_basis_k() {
    __shared__ float sB[N_RAD * 125];
    __shared__ float sNorm[N_RAD];
    int t = threadIdx.x;
    if (t < 125) {
        int z = t / 25, y = (t / 5) % 5, x = t % 5;
        float dz = (float)z - 2.0f, dy = (float)y - 2.0f, dx = (float)x - 2.0f;
        float r = sqrtf(dx * dx + dy * dy + dz * dz);
        #pragma unroll
        for (int j = 0; j < N_RAD; j++) {
            float d = (r - (float)j) * (1.0f / 0.6f);
            sB[j * 125 + t] = expf(-0.5f * d * d);
        }
    }
    __syncthreads();
    if (t < N_RAD) {
        float s = 0.0f;
        for (int i = 0; i < 125; i++) { float v = sB[t * 125 + i]; s += v * v; }
        sNorm[t] = rsqrtf(s);
    }
    __syncthreads();
    if (t < 125) {
        #pragma unroll
        for (int j = 0; j < N_RAD; j++)
            gB[j * 125 + t] = sB[j * 125 + t] * sNorm[j];
    }
}

// ---------------------------------------------------------------------------
// Kernel synthesis: K[oc][ic][t] = sum_j W[oc][ic][j] * B[j][t]
// linear index space: [0,2875) -> K0, [2875,60375) -> K1, [60375,110375) -> K2
// ---------------------------------------------------------------------------
__global__ void synth_k(const float* __restrict__ W0,
                        const float* __restrict__ W1,
                        const float* __restrict__ W2) {
    int i = blockIdx.x * blockDim.x + threadIdx.x;
    if (i < 2875) {                       // K0: [23][1][125]
        int t = i % 125, oc = i / 125;
        float s = 0.0f;
        #pragma unroll
        for (int j = 0; j < N_RAD; j++) s += W0[oc * 3 + j] * gB[j * 125 + t];
        gK0[i] = s;
    } else if (i < 2875 + 57500) {        // K1: [23][20][125]
        int k = i - 2875;
        int t = k % 125, rest = k / 125;
        int ic = rest % 20, oc = rest / 20;
        float s = 0.0f;
        #pragma unroll
        for (int j = 0; j < N_RAD; j++) s += W1[(oc * 20 + ic) * 3 + j] * gB[j * 125 + t];
        gK1[k] = s;
    } else if (i < 110375) {              // K2: [20][20][125]
        int k = i - 60375;
        int t = k % 125, rest = k / 125;
        int ic = rest % 20, oc = rest / 20;
        float s = 0.0f;
        #pragma unroll
        for (int j = 0; j < N_RAD; j++) s += W2[(oc * 20 + ic) * 3 + j] * gB[j * 125 + t];
        gK2[k] = s;
    }
}

// ---------------------------------------------------------------------------
// Tiled direct conv3d, stride 2, pad 3, kernel 5.
//  IC      : input channels
//  OCRAW   : total raw output channels of the layer
//  OCTHIS  : raw channels handled by this block (== OCRAW unless split by gridDim.y)
//  GATED   : apply capsule gating (requires OCTHIS==OCRAW==23, writes 20 ch)
//  TD/TH/TW: output tile per block; blockDim.x == TD*TH*TW
// ---------------------------------------------------------------------------
template <int IC, int OCRAW, int OCTHIS, bool GATED, int TD, int TH, int TW>
__global__ void conv_tile(const float* __restrict__ in,
                          const float* __restrict__ Ks,
                          float* __restrict__ out,
                          int inD, int inH, int inW,
                          int outD, int outH, int outW,
                          int ntD, int ntH, int ntW) {
    constexpr int SD = 2 * TD + 3, SH = 2 * TH + 3, SW = 2 * TW + 3;
    constexpr int NT = TD * TH * TW;
    __shared__ float sIn[SD * SH * SW];
    __shared__ float sK[OCTHIS * 125];

    int blk = blockIdx.x;
    int tw = blk % ntW; blk /= ntW;
    int th = blk % ntH; blk /= ntH;
    int td = blk % ntD;
    int b  = blk / ntD;
    const int oc0 = blockIdx.y * OCTHIS;

    const int oz0 = td * TD, oy0 = th * TH, ox0 = tw * TW;
    const int iz0 = 2 * oz0 - 3, iy0 = 2 * oy0 - 3, ix0 = 2 * ox0 - 3;

    const int tid = threadIdx.x;
    const int tx = tid % TW;
    const int ty = (tid / TW) % TH;
    const int tz = tid / (TW * TH);

    float acc[OCTHIS];
    #pragma unroll
    for (int oc = 0; oc < OCTHIS; oc++) acc[oc] = 0.0f;

    const size_t inVol = (size_t)inD * inH * inW;
    const float* inB = in + (size_t)b * IC * inVol;

    for (int ic = 0; ic < IC; ic++) {
        // stage input tile (zero-padded) + kernel slice for this ic
        const float* inC = inB + (size_t)ic * inVol;
        for (int i = tid; i < SD * SH * SW; i += NT) {
            int x = i % SW, y = (i / SW) % SH, z = i / (SW * SH);
            int gz = iz0 + z, gy = iy0 + y, gx = ix0 + x;
            float v = 0.0f;
            if ((unsigned)gz < (unsigned)inD && (unsigned)gy < (unsigned)inH &&
                (unsigned)gx < (unsigned)inW)
                v = inC[((size_t)gz * inH + gy) * inW + gx];
            sIn[i] = v;
        }
        for (int i = tid; i < OCTHIS * 125; i += NT) {
            int t = i % 125, oc = i / 125;
            sK[i] = Ks[((size_t)(oc0 + oc) * IC + ic) * 125 + t];
        }
        __syncthreads();

        const int base = (2 * tz) * (SH * SW) + (2 * ty) * SW + (2 * tx);
        #pragma unroll 1
        for (int kz = 0; kz < 5; kz++) {
            #pragma unroll 1
            for (int ky = 0; ky < 5; ky++) {
                const float* rowIn = &sIn[base + (kz * SH + ky) * SW];
                const float* rowK  = &sK[(kz * 5 + ky) * 5];
                #pragma unroll
                for (int kx = 0; kx < 5; kx++) {
                    float v = rowIn[kx];
                    #pragma unroll
                    for (int oc = 0; oc < OCTHIS; oc++)
                        acc[oc] += v * rowK[oc * 125 + kx];
                }
            }
        }
        __syncthreads();
    }

    const int oz = oz0 + tz, oy = oy0 + ty, ox = ox0 + tx;
    if (oz < outD && oy < outH && ox < outW) {
        const size_t vol = (size_t)outD * outH * outW;
        const size_t sp = ((size_t)oz * outH + oy) * outW + ox;
        if constexpr (GATED) {
            float* ob = out + (size_t)b * 20 * vol + sp;
            float g0 = sigmoidf_(acc[20]);
            float g1 = sigmoidf_(acc[21]);
            float g2 = sigmoidf_(acc[22]);
            #pragma unroll
            for (int c = 0; c < 5; c++)  ob[(size_t)c * vol] = fmaxf(acc[c], 0.0f);
            #pragma unroll
            for (int c = 5; c < 8; c++)  ob[(size_t)c * vol] = acc[c] * g0;
            #pragma unroll
            for (int c = 8; c < 13; c++) ob[(size_t)c * vol] = acc[c] * g1;
            #pragma unroll
            for (int c = 13; c < 20; c++) ob[(size_t)c * vol] = acc[c] * g2;
        } else {
            float* ob = out + (size_t)b * OCRAW * vol + sp;
            #pragma unroll
            for (int oc = 0; oc < OCTHIS; oc++)
                ob[(size_t)(oc0 + oc) * vol] = acc[oc];
        }
    }
}

// ---------------------------------------------------------------------------
// Head: spatial mean [16,20,1000] -> [16,20]; fc1(50)+relu; fc2(2)
// One block per batch, 160 threads (8 threads per channel for the mean).
// ---------------------------------------------------------------------------
__global__ void head_k(const float* __restrict__ act,
                       const float* __restrict__ fc1w, const float* __restrict__ fc1b,
                       const float* __restrict__ fc2w, const float* __restrict__ fc2b,
                       float* __restrict__ out) {
    __shared__ float sm[20];
    __shared__ float sh[50];
    const int b = blockIdx.x;
    const int tid = threadIdx.x;

    {
        int c = tid >> 3, lane8 = tid & 7;   // 160 threads -> 20 channels x 8
        const float* p = act + ((size_t)b * 20 + c) * 1000;
        float s = 0.0f;
        for (int i = lane8; i < 1000; i += 8) s += p[i];
        s += __shfl_down_sync(0xffffffffu, s, 4);
        s += __shfl_down_sync(0xffffffffu, s, 2);
        s += __shfl_down_sync(0xffffffffu, s, 1);
        if (lane8 == 0) sm[c] = s * (1.0f / 1000.0f);
    }
    __syncthreads();
    if (tid < 50) {
        float s = fc1b[tid];
        #pragma unroll
        for (int i = 0; i < 20; i++) s += sm[i] * fc1w[tid * 20 + i];
        sh[tid] = fmaxf(s, 0.0f);
    }
    __syncthreads();
    if (tid < 2) {
        float s = fc2b[tid];
        for (int i = 0; i < 50; i++) s += sh[i] * fc2w[tid * 50 + i];
        out[b * 2 + tid] = s;
    }
}

// ---------------------------------------------------------------------------
extern "C" void kernel_launch(void* const* d_in, const int* in_sizes, int n_in,
                              void* d_out, int out_size) {
    const float* inp   = (const float*)d_in[0];
    const float* W0    = (const float*)d_in[1];
    const float* W1    = (const float*)d_in[2];
    const float* W2    = (const float*)d_in[3];
    const float* fc1_w = (const float*)d_in[4];
    const float* fc1_b = (const float*)d_in[5];
    const float* fc2_w = (const float*)d_in[6];
    const float* fc2_b = (const float*)d_in[7];
    float* out = (float*)d_out;

    float *pK0, *pK1, *pK2, *pA0, *pA1, *pA2;
    cudaGetSymbolAddress((void**)&pK0, gK0);
    cudaGetSymbolAddress((void**)&pK1, gK1);
    cudaGetSymbolAddress((void**)&pK2, gK2);
    cudaGetSymbolAddress((void**)&pA0, gA0);
    cudaGetSymbolAddress((void**)&pA1, gA1);
    cudaGetSymbolAddress((void**)&pA2, gA2);

    init_basis_k<<<1, 128>>>();
    synth_k<<<(110375 + 255) / 256, 256>>>(W0, W1, W2);

    // L0: out 33^3, tile (4,8,8) -> tiles (9,5,5), 3600 blocks, 256 thr
    conv_tile<1, 23, 23, true, 4, 8, 8>
        <<<dim3(16 * 9 * 5 * 5, 1), 256>>>(inp, pK0, pA0,
                                           64, 64, 64, 33, 33, 33, 9, 5, 5);
    // L1: out 18^3, tile (6,6,6) -> tiles (3,3,3), 432 blocks, 216 thr
    conv_tile<20, 23, 23, true, 6, 6, 6>
        <<<dim3(16 * 27, 1), 216>>>(pA0, pK1, pA1,
                                    33, 33, 33, 18, 18, 18, 3, 3, 3);
    // L2: out 10^3, tile (5,5,5) -> tiles (2,2,2), oc split 2 -> 128x2 blocks
    conv_tile<20, 20, 10, false, 5, 5, 5>
        <<<dim3(16 * 8, 2), 125>>>(pA1, pK2, pA2,
                                   18, 18, 18, 10, 10, 10, 2, 2, 2);

    head_k<<<16, 160>>>(pA2, fc1_w, fc1_b, fc2_w, fc2_b, out);
}

// round 2
// speedup vs baseline: 1.8109x; 1.8109x over previous
#include <cuda_runtime.h>
#include <math.h>

// ---------------------------------------------------------------------------
// CNN_51015621542651: 3x (radial-basis conv3d stride2 pad3 size5) + gating,
// spatial mean, fc1+relu, fc2.  Batch 16, input [16,1,64,64,64].
// R2: tap-major smem kernel layout (float4 broadcast LDS) + T=2 x-register
//     tiling; L2 ic-split x4 with linear combine in the head.
// ---------------------------------------------------------------------------

#define N_RAD 3

__device__ float gB[N_RAD * 125];
__device__ float gK0[23 * 1 * 125];
__device__ float gK1[23 * 20 * 125];
__device__ float gK2[20 * 20 * 125];
__device__ float gA0[16 * 20 * 33 * 33 * 33];
__device__ float gA1[16 * 20 * 18 * 18 * 18];
__device__ float gA2[4 * 16 * 20 * 1000];      // 4 ic-group partials for L2

__device__ __forceinline__ float sigmoidf_(float x) {
    return 1.0f / (1.0f + expf(-x));
}

// ---------------------------------------------------------------------------
__global__ void init_basis_k() {
    __shared__ float sB[N_RAD * 125];
    __shared__ float sNorm[N_RAD];
    int t = threadIdx.x;
    if (t < 125) {
        int z = t / 25, y = (t / 5) % 5, x = t % 5;
        float dz = (float)z - 2.0f, dy = (float)y - 2.0f, dx = (float)x - 2.0f;
        float r = sqrtf(dx * dx + dy * dy + dz * dz);
        #pragma unroll
        for (int j = 0; j < N_RAD; j++) {
            float d = (r - (float)j) * (1.0f / 0.6f);
            sB[j * 125 + t] = expf(-0.5f * d * d);
        }
    }
    __syncthreads();
    if (t < N_RAD) {
        float s = 0.0f;
        for (int i = 0; i < 125; i++) { float v = sB[t * 125 + i]; s += v * v; }
        sNorm[t] = rsqrtf(s);
    }
    __syncthreads();
    if (t < 125) {
        #pragma unroll
        for (int j = 0; j < N_RAD; j++)
            gB[j * 125 + t] = sB[j * 125 + t] * sNorm[j];
    }
}

__global__ void synth_k(const float* __restrict__ W0,
                        const float* __restrict__ W1,
                        const float* __restrict__ W2) {
    int i = blockIdx.x * blockDim.x + threadIdx.x;
    if (i < 2875) {
        int t = i % 125, oc = i / 125;
        float s = 0.0f;
        #pragma unroll
        for (int j = 0; j < N_RAD; j++) s += W0[oc * 3 + j] * gB[j * 125 + t];
        gK0[i] = s;
    } else if (i < 2875 + 57500) {
        int k = i - 2875;
        int t = k % 125, rest = k / 125;
        int ic = rest % 20, oc = rest / 20;
        float s = 0.0f;
        #pragma unroll
        for (int j = 0; j < N_RAD; j++) s += W1[(oc * 20 + ic) * 3 + j] * gB[j * 125 + t];
        gK1[k] = s;
    } else if (i < 110375) {
        int k = i - 60375;
        int t = k % 125, rest = k / 125;
        int ic = rest % 20, oc = rest / 20;
        float s = 0.0f;
        #pragma unroll
        for (int j = 0; j < N_RAD; j++) s += W2[(oc * 20 + ic) * 3 + j] * gB[j * 125 + t];
        gK2[k] = s;
    }
}

// ---------------------------------------------------------------------------
// Conv3d stride 2, pad 3, k=5. Each thread computes 2 adjacent x-outputs.
//  IC_TOTAL : total input channels of layer (kernel tensor stride)
//  ICG      : input channels handled by this block (ic-split via blockIdx.y)
//  OCRAW    : raw output channels
//  OC_PAD   : OCRAW rounded up to multiple of 4 (smem tap-row width)
//  GATED    : capsule gating epilogue (requires OCRAW==23)
//  TD/TH/TW : output tile per block; blockDim.x = TD*TH*(TW/2)
// ---------------------------------------------------------------------------
template <int IC_TOTAL, int ICG, int OCRAW, int OC_PAD, bool GATED,
          int TD, int TH, int TW>
__global__ void conv_t2(const float* __restrict__ in,
                        const float* __restrict__ Ks,
                        float* __restrict__ out,
                        int inD, int inH, int inW,
                        int outD, int outH, int outW,
                        int ntD, int ntH, int ntW,
                        size_t outGroupStride) {
    constexpr int SD = 2 * TD + 3, SH = 2 * TH + 3, SW = 2 * TW + 3;
    constexpr int TXT = TW / 2;
    constexpr int NT = TD * TH * TXT;
    constexpr int NQ = OC_PAD / 4;

    __shared__ float sIn[SD * SH * SW];
    __shared__ __align__(16) float sK[125 * OC_PAD];

    int blk = blockIdx.x;
    int tw = blk % ntW; blk /= ntW;
    int th = blk % ntH; blk /= ntH;
    int td = blk % ntD;
    int b  = blk / ntD;
    const int icBegin = blockIdx.y * ICG;

    const int oz0 = td * TD, oy0 = th * TH, ox0 = tw * TW;
    const int iz0 = 2 * oz0 - 3, iy0 = 2 * oy0 - 3, ix0 = 2 * ox0 - 3;

    const int tid = threadIdx.x;
    const int txl = tid % TXT;
    const int ty  = (tid / TXT) % TH;
    const int tz  = tid / (TXT * TH);

    float2 acc[OC_PAD];
    #pragma unroll
    for (int oc = 0; oc < OC_PAD; oc++) acc[oc] = make_float2(0.0f, 0.0f);

    const size_t inVol = (size_t)inD * inH * inW;
    const float* inB = in + (size_t)b * IC_TOTAL * inVol;

    for (int icl = 0; icl < ICG; icl++) {
        const int ic = icBegin + icl;
        const float* inC = inB + (size_t)ic * inVol;
        for (int i = tid; i < SD * SH * SW; i += NT) {
            int x = i % SW, y = (i / SW) % SH, z = i / (SW * SH);
            int gz = iz0 + z, gy = iy0 + y, gx = ix0 + x;
            float v = 0.0f;
            if ((unsigned)gz < (unsigned)inD && (unsigned)gy < (unsigned)inH &&
                (unsigned)gx < (unsigned)inW)
                v = inC[((size_t)gz * inH + gy) * inW + gx];
            sIn[i] = v;
        }
        // tap-major kernel slice: sK[t*OC_PAD + oc]
        for (int i = tid; i < 125 * OC_PAD; i += NT) {
            int oc = i % OC_PAD, t = i / OC_PAD;
            sK[i] = (oc < OCRAW)
                        ? Ks[((size_t)oc * IC_TOTAL + ic) * 125 + t]
                        : 0.0f;
        }
        __syncthreads();

        const float* rowBase =
            &sIn[(2 * tz) * (SH * SW) + (2 * ty) * SW + 4 * txl];
        #pragma unroll 1
        for (int kz = 0; kz < 5; kz++) {
            #pragma unroll 1
            for (int ky = 0; ky < 5; ky++) {
                const float* r = rowBase + (kz * SH + ky) * SW;
                float v[7];
                #pragma unroll
                for (int i = 0; i < 7; i++) v[i] = r[i];
                const float4* kp =
                    (const float4*)&sK[((kz * 5 + ky) * 5) * OC_PAD];
                #pragma unroll
                for (int kx = 0; kx < 5; kx++) {
                    const float vA = v[kx];
                    const float vB = v[kx + 2];
                    #pragma unroll
                    for (int q = 0; q < NQ; q++) {
                        float4 k4 = kp[kx * NQ + q];
                        acc[4 * q + 0].x += k4.x * vA;
                        acc[4 * q + 0].y += k4.x * vB;
                        acc[4 * q + 1].x += k4.y * vA;
                        acc[4 * q + 1].y += k4.y * vB;
                        acc[4 * q + 2].x += k4.z * vA;
                        acc[4 * q + 2].y += k4.z * vB;
                        acc[4 * q + 3].x += k4.w * vA;
                        acc[4 * q + 3].y += k4.w * vB;
                    }
                }
            }
        }
        __syncthreads();
    }

    const int oz = oz0 + tz, oy = oy0 + ty, oxA = ox0 + 2 * txl;
    if (oz < outD && oy < outH) {
        const size_t vol = (size_t)outD * outH * outW;
        const bool wA = (oxA < outW), wB = (oxA + 1 < outW);
        const size_t spA = ((size_t)oz * outH + oy) * outW + oxA;
        if constexpr (GATED) {
            float* ob = out + (size_t)b * 20 * vol + spA;
            float g0A = sigmoidf_(acc[20].x), g0B = sigmoidf_(acc[20].y);
            float g1A = sigmoidf_(acc[21].x), g1B = sigmoidf_(acc[21].y);
            float g2A = sigmoidf_(acc[22].x), g2B = sigmoidf_(acc[22].y);
            #pragma unroll
            for (int c = 0; c < 20; c++) {
                float a = acc[c].x, bb = acc[c].y;
                if (c < 5)       { a = fmaxf(a, 0.0f); bb = fmaxf(bb, 0.0f); }
                else if (c < 8)  { a *= g0A; bb *= g0B; }
                else if (c < 13) { a *= g1A; bb *= g1B; }
                else             { a *= g2A; bb *= g2B; }
                if (wA) ob[(size_t)c * vol]     = a;
                if (wB) ob[(size_t)c * vol + 1] = bb;
            }
        } else {
            float* ob = out + (size_t)blockIdx.y * outGroupStride +
                        (size_t)b * OCRAW * vol + spA;
            #pragma unroll
            for (int oc = 0; oc < OCRAW; oc++) {
                if (wA) ob[(size_t)oc * vol]     = acc[oc].x;
                if (wB) ob[(size_t)oc * vol + 1] = acc[oc].y;
            }
        }
    }
}

// ---------------------------------------------------------------------------
// Head: combine 4 L2 ic-group partials, spatial mean, fc1+relu, fc2.
// ---------------------------------------------------------------------------
__global__ void head_k(const float* __restrict__ act,
                       const float* __restrict__ fc1w, const float* __restrict__ fc1b,
                       const float* __restrict__ fc2w, const float* __restrict__ fc2b,
                       float* __restrict__ out) {
    __shared__ float sm[20];
    __shared__ float sh[50];
    const int b = blockIdx.x;
    const int tid = threadIdx.x;

    {
        int c = tid >> 3, lane8 = tid & 7;
        float s = 0.0f;
        #pragma unroll
        for (int g = 0; g < 4; g++) {
            const float* p = act + (((size_t)g * 16 + b) * 20 + c) * 1000;
            for (int i = lane8; i < 1000; i += 8) s += p[i];
        }
        s += __shfl_down_sync(0xffffffffu, s, 4);
        s += __shfl_down_sync(0xffffffffu, s, 2);
        s += __shfl_down_sync(0xffffffffu, s, 1);
        if (lane8 == 0) sm[c] = s * (1.0f / 1000.0f);
    }
    __syncthreads();
    if (tid < 50) {
        float s = fc1b[tid];
        #pragma unroll
        for (int i = 0; i < 20; i++) s += sm[i] * fc1w[tid * 20 + i];
        sh[tid] = fmaxf(s, 0.0f);
    }
    __syncthreads();
    if (tid < 2) {
        float s = fc2b[tid];
        for (int i = 0; i < 50; i++) s += sh[i] * fc2w[tid * 50 + i];
        out[b * 2 + tid] = s;
    }
}

// ---------------------------------------------------------------------------
extern "C" void kernel_launch(void* const* d_in, const int* in_sizes, int n_in,
                              void* d_out, int out_size) {
    const float* inp   = (const float*)d_in[0];
    const float* W0    = (const float*)d_in[1];
    const float* W1    = (const float*)d_in[2];
    const float* W2    = (const float*)d_in[3];
    const float* fc1_w = (const float*)d_in[4];
    const float* fc1_b = (const float*)d_in[5];
    const float* fc2_w = (const float*)d_in[6];
    const float* fc2_b = (const float*)d_in[7];
    float* out = (float*)d_out;

    float *pK0, *pK1, *pK2, *pA0, *pA1, *pA2;
    cudaGetSymbolAddress((void**)&pK0, gK0);
    cudaGetSymbolAddress((void**)&pK1, gK1);
    cudaGetSymbolAddress((void**)&pK2, gK2);
    cudaGetSymbolAddress((void**)&pA0, gA0);
    cudaGetSymbolAddress((void**)&pA1, gA1);
    cudaGetSymbolAddress((void**)&pA2, gA2);

    init_basis_k<<<1, 128>>>();
    synth_k<<<(110375 + 255) / 256, 256>>>(W0, W1, W2);

    // L0: out 33^3, tile (4,8,8) -> nt (9,5,5), 3600 blocks x 128 thr
    conv_t2<1, 1, 23, 24, true, 4, 8, 8>
        <<<dim3(16 * 9 * 5 * 5, 1), 4 * 8 * 4>>>(
            inp, pK0, pA0, 64, 64, 64, 33, 33, 33, 9, 5, 5, 0);

    // L1: out 18^3, tile (6,6,6) -> nt (3,3,3), 432 blocks x 108 thr
    conv_t2<20, 20, 23, 24, true, 6, 6, 6>
        <<<dim3(16 * 27, 1), 6 * 6 * 3>>>(
            pA0, pK1, pA1, 33, 33, 33, 18, 18, 18, 3, 3, 3, 0);

    // L2: out 10^3, tile (5,5,10) -> nt (2,2,1), ic-split 4 -> 64x4 blocks
    conv_t2<20, 5, 20, 20, false, 5, 5, 10>
        <<<dim3(16 * 4, 4), 5 * 5 * 5>>>(
            pA1, pK2, pA2, 18, 18, 18, 10, 10, 10, 2, 2, 1,
            (size_t)16 * 20 * 1000);

    head_k<<<16, 160>>>(pA2, fc1_w, fc1_b, fc2_w, fc2_b, out);
}

// round 3
// speedup vs baseline: 2.0784x; 1.1477x over previous
#include <cuda_runtime.h>
#include <math.h>

// ---------------------------------------------------------------------------
// CNN_51015621542651  —  R3
//  - L1 ic-split x4 into raw partials + combine/gate kernel (occupancy fix)
//  - L2 ic-split x10, head combines 10 groups
//  - padded smem rows -> float4 input loads
// ---------------------------------------------------------------------------

#define N_RAD 3

__device__ float gB[N_RAD * 125];
__device__ float gK0[23 * 1 * 125];
__device__ float gK1[23 * 20 * 125];
__device__ float gK2[20 * 20 * 125];
__device__ float gA0[16 * 20 * 33 * 33 * 33];          // L0 gated out
__device__ float gP1[4 * 16 * 23 * 18 * 18 * 18];      // L1 raw partials (4 ic-groups)
__device__ float gA1[16 * 20 * 18 * 18 * 18];          // L1 gated out
__device__ float gA2[10 * 16 * 20 * 1000];             // L2 partials (10 ic-groups)

__device__ __forceinline__ float sigmoidf_(float x) {
    return 1.0f / (1.0f + expf(-x));
}

// ---------------------------------------------------------------------------
__global__ void init_basis_k() {
    __shared__ float sB[N_RAD * 125];
    __shared__ float sNorm[N_RAD];
    int t = threadIdx.x;
    if (t < 125) {
        int z = t / 25, y = (t / 5) % 5, x = t % 5;
        float dz = (float)z - 2.0f, dy = (float)y - 2.0f, dx = (float)x - 2.0f;
        float r = sqrtf(dx * dx + dy * dy + dz * dz);
        #pragma unroll
        for (int j = 0; j < N_RAD; j++) {
            float d = (r - (float)j) * (1.0f / 0.6f);
            sB[j * 125 + t] = expf(-0.5f * d * d);
        }
    }
    __syncthreads();
    if (t < N_RAD) {
        float s = 0.0f;
        for (int i = 0; i < 125; i++) { float v = sB[t * 125 + i]; s += v * v; }
        sNorm[t] = rsqrtf(s);
    }
    __syncthreads();
    if (t < 125) {
        #pragma unroll
        for (int j = 0; j < N_RAD; j++)
            gB[j * 125 + t] = sB[j * 125 + t] * sNorm[j];
    }
}

__global__ void synth_k(const float* __restrict__ W0,
                        const float* __restrict__ W1,
                        const float* __restrict__ W2) {
    int i = blockIdx.x * blockDim.x + threadIdx.x;
    if (i < 2875) {
        int t = i % 125, oc = i / 125;
        float s = 0.0f;
        #pragma unroll
        for (int j = 0; j < N_RAD; j++) s += W0[oc * 3 + j] * gB[j * 125 + t];
        gK0[i] = s;
    } else if (i < 2875 + 57500) {
        int k = i - 2875;
        int t = k % 125, rest = k / 125;
        int ic = rest % 20, oc = rest / 20;
        float s = 0.0f;
        #pragma unroll
        for (int j = 0; j < N_RAD; j++) s += W1[(oc * 20 + ic) * 3 + j] * gB[j * 125 + t];
        gK1[k] = s;
    } else if (i < 110375) {
        int k = i - 60375;
        int t = k % 125, rest = k / 125;
        int ic = rest % 20, oc = rest / 20;
        float s = 0.0f;
        #pragma unroll
        for (int j = 0; j < N_RAD; j++) s += W2[(oc * 20 + ic) * 3 + j] * gB[j * 125 + t];
        gK2[k] = s;
    }
}

// ---------------------------------------------------------------------------
// Conv3d stride 2, pad 3, k=5; thread computes 2 adjacent x-outputs.
// Smem input rows padded to multiple of 4 floats -> float4 loads.
// ---------------------------------------------------------------------------
template <int IC_TOTAL, int ICG, int OCRAW, int OC_PAD, bool GATED,
          int TD, int TH, int TW>
__global__ void conv_t2(const float* __restrict__ in,
                        const float* __restrict__ Ks,
                        float* __restrict__ out,
                        int inD, int inH, int inW,
                        int outD, int outH, int outW,
                        int ntD, int ntH, int ntW,
                        size_t outGroupStride) {
    constexpr int SD = 2 * TD + 3, SH = 2 * TH + 3, SW = 2 * TW + 3;
    constexpr int SWP = (SW + 3) & ~3;
    constexpr int TXT = TW / 2;
    constexpr int NT = TD * TH * TXT;
    constexpr int NQ = OC_PAD / 4;

    __shared__ __align__(16) float sIn[SD * SH * SWP];
    __shared__ __align__(16) float sK[125 * OC_PAD];

    int blk = blockIdx.x;
    int tw = blk % ntW; blk /= ntW;
    int th = blk % ntH; blk /= ntH;
    int td = blk % ntD;
    int b  = blk / ntD;
    const int icBegin = blockIdx.y * ICG;

    const int oz0 = td * TD, oy0 = th * TH, ox0 = tw * TW;
    const int iz0 = 2 * oz0 - 3, iy0 = 2 * oy0 - 3, ix0 = 2 * ox0 - 3;

    const int tid = threadIdx.x;
    const int txl = tid % TXT;
    const int ty  = (tid / TXT) % TH;
    const int tz  = tid / (TXT * TH);

    float2 acc[OC_PAD];
    #pragma unroll
    for (int oc = 0; oc < OC_PAD; oc++) acc[oc] = make_float2(0.0f, 0.0f);

    const size_t inVol = (size_t)inD * inH * inW;
    const float* inB = in + (size_t)b * IC_TOTAL * inVol;

    for (int icl = 0; icl < ICG; icl++) {
        const int ic = icBegin + icl;
        const float* inC = inB + (size_t)ic * inVol;
        for (int i = tid; i < SD * SH * SWP; i += NT) {
            int x = i % SWP, y = (i / SWP) % SH, z = i / (SWP * SH);
            int gz = iz0 + z, gy = iy0 + y, gx = ix0 + x;
            float v = 0.0f;
            if (x < SW && (unsigned)gz < (unsigned)inD &&
                (unsigned)gy < (unsigned)inH && (unsigned)gx < (unsigned)inW)
                v = inC[((size_t)gz * inH + gy) * inW + gx];
            sIn[i] = v;
        }
        for (int i = tid; i < 125 * OC_PAD; i += NT) {
            int oc = i % OC_PAD, t = i / OC_PAD;
            sK[i] = (oc < OCRAW)
                        ? Ks[((size_t)oc * IC_TOTAL + ic) * 125 + t]
                        : 0.0f;
        }
        __syncthreads();

        const float* rowBase =
            &sIn[(2 * tz) * (SH * SWP) + (2 * ty) * SWP + 4 * txl];
        #pragma unroll 1
        for (int kz = 0; kz < 5; kz++) {
            #pragma unroll 1
            for (int ky = 0; ky < 5; ky++) {
                const float4* r4 =
                    (const float4*)(rowBase + (kz * SH + ky) * SWP);
                float4 f0 = r4[0], f1 = r4[1];
                float v[8] = {f0.x, f0.y, f0.z, f0.w, f1.x, f1.y, f1.z, f1.w};
                const float4* kp =
                    (const float4*)&sK[((kz * 5 + ky) * 5) * OC_PAD];
                #pragma unroll
                for (int kx = 0; kx < 5; kx++) {
                    const float vA = v[kx];
                    const float vB = v[kx + 2];
                    #pragma unroll
                    for (int q = 0; q < NQ; q++) {
                        float4 k4 = kp[kx * NQ + q];
                        acc[4 * q + 0].x += k4.x * vA;
                        acc[4 * q + 0].y += k4.x * vB;
                        acc[4 * q + 1].x += k4.y * vA;
                        acc[4 * q + 1].y += k4.y * vB;
                        acc[4 * q + 2].x += k4.z * vA;
                        acc[4 * q + 2].y += k4.z * vB;
                        acc[4 * q + 3].x += k4.w * vA;
                        acc[4 * q + 3].y += k4.w * vB;
                    }
                }
            }
        }
        __syncthreads();
    }

    const int oz = oz0 + tz, oy = oy0 + ty, oxA = ox0 + 2 * txl;
    if (oz < outD && oy < outH) {
        const size_t vol = (size_t)outD * outH * outW;
        const bool wA = (oxA < outW), wB = (oxA + 1 < outW);
        const size_t spA = ((size_t)oz * outH + oy) * outW + oxA;
        if constexpr (GATED) {
            float* ob = out + (size_t)b * 20 * vol + spA;
            float g0A = sigmoidf_(acc[20].x), g0B = sigmoidf_(acc[20].y);
            float g1A = sigmoidf_(acc[21].x), g1B = sigmoidf_(acc[21].y);
            float g2A = sigmoidf_(acc[22].x), g2B = sigmoidf_(acc[22].y);
            #pragma unroll
            for (int c = 0; c < 20; c++) {
                float a = acc[c].x, bb = acc[c].y;
                if (c < 5)       { a = fmaxf(a, 0.0f); bb = fmaxf(bb, 0.0f); }
                else if (c < 8)  { a *= g0A; bb *= g0B; }
                else if (c < 13) { a *= g1A; bb *= g1B; }
                else             { a *= g2A; bb *= g2B; }
                if (wA) ob[(size_t)c * vol]     = a;
                if (wB) ob[(size_t)c * vol + 1] = bb;
            }
        } else {
            float* ob = out + (size_t)blockIdx.y * outGroupStride +
                        (size_t)b * OCRAW * vol + spA;
            #pragma unroll
            for (int oc = 0; oc < OCRAW; oc++) {
                if (wA) ob[(size_t)oc * vol]     = acc[oc].x;
                if (wB) ob[(size_t)oc * vol + 1] = acc[oc].y;
            }
        }
    }
}

// ---------------------------------------------------------------------------
// Combine 4 raw L1 partials [4,16,23,V] -> gated [16,20,V]  (V = 18^3)
// ---------------------------------------------------------------------------
__global__ void combine_gate_k(const float* __restrict__ P,
                               float* __restrict__ out) {
    constexpr int V = 18 * 18 * 18;
    int idx = blockIdx.x * blockDim.x + threadIdx.x;
    if (idx >= 16 * V) return;
    int b = idx / V, sp = idx % V;
    float v[23];
    #pragma unroll
    for (int c = 0; c < 23; c++) {
        float s = 0.0f;
        #pragma unroll
        for (int g = 0; g < 4; g++)
            s += P[(((size_t)g * 16 + b) * 23 + c) * V + sp];
        v[c] = s;
    }
    float g0 = sigmoidf_(v[20]), g1 = sigmoidf_(v[21]), g2 = sigmoidf_(v[22]);
    float* ob = out + ((size_t)b * 20) * V + sp;
    #pragma unroll
    for (int c = 0; c < 20; c++) {
        float a = v[c];
        if (c < 5)       a = fmaxf(a, 0.0f);
        else if (c < 8)  a *= g0;
        else if (c < 13) a *= g1;
        else             a *= g2;
        ob[(size_t)c * V] = a;
    }
}

// ---------------------------------------------------------------------------
// Head: combine 10 L2 ic-group partials, mean, fc1+relu, fc2.
// ---------------------------------------------------------------------------
__global__ void head_k(const float* __restrict__ act,
                       const float* __restrict__ fc1w, const float* __restrict__ fc1b,
                       const float* __restrict__ fc2w, const float* __restrict__ fc2b,
                       float* __restrict__ out) {
    __shared__ float sm[20];
    __shared__ float sh[50];
    const int b = blockIdx.x;
    const int tid = threadIdx.x;

    {
        int c = tid >> 3, lane8 = tid & 7;
        float s = 0.0f;
        #pragma unroll
        for (int g = 0; g < 10; g++) {
            const float* p = act + (((size_t)g * 16 + b) * 20 + c) * 1000;
            for (int i = lane8; i < 1000; i += 8) s += p[i];
        }
        s += __shfl_down_sync(0xffffffffu, s, 4);
        s += __shfl_down_sync(0xffffffffu, s, 2);
        s += __shfl_down_sync(0xffffffffu, s, 1);
        if (lane8 == 0) sm[c] = s * (1.0f / 1000.0f);
    }
    __syncthreads();
    if (tid < 50) {
        float s = fc1b[tid];
        #pragma unroll
        for (int i = 0; i < 20; i++) s += sm[i] * fc1w[tid * 20 + i];
        sh[tid] = fmaxf(s, 0.0f);
    }
    __syncthreads();
    if (tid < 2) {
        float s = fc2b[tid];
        for (int i = 0; i < 50; i++) s += sh[i] * fc2w[tid * 50 + i];
        out[b * 2 + tid] = s;
    }
}

// ---------------------------------------------------------------------------
extern "C" void kernel_launch(void* const* d_in, const int* in_sizes, int n_in,
                              void* d_out, int out_size) {
    const float* inp   = (const float*)d_in[0];
    const float* W0    = (const float*)d_in[1];
    const float* W1    = (const float*)d_in[2];
    const float* W2    = (const float*)d_in[3];
    const float* fc1_w = (const float*)d_in[4];
    const float* fc1_b = (const float*)d_in[5];
    const float* fc2_w = (const float*)d_in[6];
    const float* fc2_b = (const float*)d_in[7];
    float* out = (float*)d_out;

    float *pK0, *pK1, *pK2, *pA0, *pP1, *pA1, *pA2;
    cudaGetSymbolAddress((void**)&pK0, gK0);
    cudaGetSymbolAddress((void**)&pK1, gK1);
    cudaGetSymbolAddress((void**)&pK2, gK2);
    cudaGetSymbolAddress((void**)&pA0, gA0);
    cudaGetSymbolAddress((void**)&pP1, gP1);
    cudaGetSymbolAddress((void**)&pA1, gA1);
    cudaGetSymbolAddress((void**)&pA2, gA2);

    init_basis_k<<<1, 128>>>();
    synth_k<<<(110375 + 255) / 256, 256>>>(W0, W1, W2);

    // L0: out 33^3, tile (4,8,8) -> nt (9,5,5), 3600 blocks x 128 thr, gated
    conv_t2<1, 1, 23, 24, true, 4, 8, 8>
        <<<dim3(16 * 9 * 5 * 5, 1), 4 * 8 * 4>>>(
            inp, pK0, pA0, 64, 64, 64, 33, 33, 33, 9, 5, 5, 0);

    // L1: out 18^3, tile (6,6,6), ic-split x4 -> 432x4 blocks x 108 thr, raw
    conv_t2<20, 5, 23, 24, false, 6, 6, 6>
        <<<dim3(16 * 27, 4), 6 * 6 * 3>>>(
            pA0, pK1, pP1, 33, 33, 33, 18, 18, 18, 3, 3, 3,
            (size_t)16 * 23 * 18 * 18 * 18);

    // combine + gate -> gA1 [16,20,18^3]
    combine_gate_k<<<(16 * 18 * 18 * 18 + 255) / 256, 256>>>(pP1, pA1);

    // L2: out 10^3, tile (5,5,10), ic-split x10 -> 64x10 blocks x 125 thr
    conv_t2<20, 2, 20, 20, false, 5, 5, 10>
        <<<dim3(16 * 4, 10), 5 * 5 * 5>>>(
            pA1, pK2, pA2, 18, 18, 18, 10, 10, 10, 2, 2, 1,
            (size_t)16 * 20 * 1000);

    head_k<<<16, 160>>>(pA2, fc1_w, fc1_b, fc2_w, fc2_b, out);
}